// round 10
// baseline (speedup 1.0000x reference)
#include <cuda_runtime.h>
#include <cuda_bf16.h>
#include <math.h>

#define BB 8
#define NN 2048
#define CC 128
#define DD 64
#define NH 1024
#define ASTR 72
#define BSTR 72

// dynamic smem layout for k_main (bytes)
#define A_BUF_BYTES (128 * ASTR * 2)          // 18432
#define B_BUF_BYTES (64 * BSTR * 2)           // 9216
#define B_BASE_OFF  (2 * A_BUF_BYTES)         // 36864
#define DSMEM_BYTES (2 * A_BUF_BYTES + 2 * B_BUF_BYTES)  // 55296

// Scratch (device globals: no allocation allowed)
__device__ float g_H[BB * NN * DD];        // hidden [B,N,D] fp32
__device__ float g_s1[BB * NN];
__device__ float g_s2[BB * NN];
__device__ float g_e[BB * NN];             // exp(t - max), period-1024 duplicated
__device__ unsigned char g_adj8[NN * NN];  // adj as 0/1 bytes
__device__ float g_w[2][BB][NN];           // per-row softmax weights [wA|wB][b][i]
__device__ __nv_bfloat16 g_Hv[2][BB * NN * DD];  // [0]=bf16(H), [1]=bf16(e*H)

__device__ __forceinline__ unsigned pack2bf(float a, float b) {
    __nv_bfloat162 t = __floats2bfloat162_rn(a, b);
    return *(unsigned*)&t;
}

// ---------------------------------------------------------------------------
// Kernel 1: H = x @ W (64x64 tile, 4x4 micro); epilogue also writes
// g_Hv[0]=bf16(H) and folds the s1/s2 dot products.
// ---------------------------------------------------------------------------
__global__ __launch_bounds__(256) void k_hidden(const float* __restrict__ x,
                                                const float* __restrict__ Wm,
                                                const float* __restrict__ av) {
    __shared__ float xs[64][32];   // 8KB
    __shared__ float Ws[CC][DD];   // 32KB
    int tid = threadIdx.x;
    int tx = tid & 15, ty = tid >> 4;
    int tx4 = tx * 4, ty4 = ty * 4;
    int i0 = blockIdx.x * 64;

    const float4* wg = (const float4*)Wm;
    float4* ws4 = (float4*)Ws;
#pragma unroll
    for (int q = 0; q < 8; q++) ws4[tid + q * 256] = wg[tid + q * 256];

    const float4* xg4 = (const float4*)(x + (size_t)i0 * CC);
    float4* xs4 = (float4*)xs;

    float acc[4][4] = {};

#pragma unroll
    for (int kc = 0; kc < 4; kc++) {
        __syncthreads();
#pragma unroll
        for (int q = 0; q < 2; q++) {
            int idx = tid + q * 256;
            int row = idx >> 3;
            int c4  = idx & 7;
            xs4[row * 8 + c4] = xg4[row * 32 + kc * 8 + c4];
        }
        __syncthreads();
#pragma unroll 8
        for (int k = 0; k < 32; k++) {
            int kk = kc * 32 + k;
            float4 bf = *(const float4*)&Ws[kk][tx4];
            float a0 = xs[ty4 + 0][k];
            float a1 = xs[ty4 + 1][k];
            float a2 = xs[ty4 + 2][k];
            float a3 = xs[ty4 + 3][k];
            acc[0][0] = fmaf(a0, bf.x, acc[0][0]);
            acc[0][1] = fmaf(a0, bf.y, acc[0][1]);
            acc[0][2] = fmaf(a0, bf.z, acc[0][2]);
            acc[0][3] = fmaf(a0, bf.w, acc[0][3]);
            acc[1][0] = fmaf(a1, bf.x, acc[1][0]);
            acc[1][1] = fmaf(a1, bf.y, acc[1][1]);
            acc[1][2] = fmaf(a1, bf.z, acc[1][2]);
            acc[1][3] = fmaf(a1, bf.w, acc[1][3]);
            acc[2][0] = fmaf(a2, bf.x, acc[2][0]);
            acc[2][1] = fmaf(a2, bf.y, acc[2][1]);
            acc[2][2] = fmaf(a2, bf.z, acc[2][2]);
            acc[2][3] = fmaf(a2, bf.w, acc[2][3]);
            acc[3][0] = fmaf(a3, bf.x, acc[3][0]);
            acc[3][1] = fmaf(a3, bf.y, acc[3][1]);
            acc[3][2] = fmaf(a3, bf.z, acc[3][2]);
            acc[3][3] = fmaf(a3, bf.w, acc[3][3]);
        }
    }

    float a1v0 = av[tx4 + 0], a1v1 = av[tx4 + 1], a1v2 = av[tx4 + 2], a1v3 = av[tx4 + 3];
    float a2v0 = av[DD + tx4 + 0], a2v1 = av[DD + tx4 + 1], a2v2 = av[DD + tx4 + 2], a2v3 = av[DD + tx4 + 3];

#pragma unroll
    for (int ii = 0; ii < 4; ii++) {
        int row = i0 + ty4 + ii;
        *(float4*)&g_H[(size_t)row * DD + tx4] =
            make_float4(acc[ii][0], acc[ii][1], acc[ii][2], acc[ii][3]);
        *(uint2*)&g_Hv[0][(size_t)row * DD + tx4] =
            make_uint2(pack2bf(acc[ii][0], acc[ii][1]), pack2bf(acc[ii][2], acc[ii][3]));
        float p1 = acc[ii][0] * a1v0 + acc[ii][1] * a1v1 + acc[ii][2] * a1v2 + acc[ii][3] * a1v3;
        float p2 = acc[ii][0] * a2v0 + acc[ii][1] * a2v1 + acc[ii][2] * a2v2 + acc[ii][3] * a2v3;
#pragma unroll
        for (int o = 8; o > 0; o >>= 1) {
            p1 += __shfl_xor_sync(0xffffffffu, p1, o);
            p2 += __shfl_xor_sync(0xffffffffu, p2, o);
        }
        if (tx == 0) { g_s1[row] = p1; g_s2[row] = p2; }
    }
}

// ---------------------------------------------------------------------------
// Kernel 2: e[j] = exp(lrelu(s1[2j]+s2[2j+1]) - max) per batch, period 1024.
// ---------------------------------------------------------------------------
__global__ __launch_bounds__(256) void k_prep() {
    int b = blockIdx.x;
    __shared__ float ts[NH];
    __shared__ float red[256];
    const float* s1 = g_s1 + b * NN;
    const float* s2 = g_s2 + b * NN;
    int tid = threadIdx.x;

    float mx = -1e30f;
    for (int j = tid; j < NH; j += 256) {
        float v = s1[2 * j] + s2[2 * j + 1];
        v = v > 0.f ? v : 0.2f * v;
        ts[j] = v;
        mx = fmaxf(mx, v);
    }
    red[tid] = mx;
    __syncthreads();
    for (int o = 128; o > 0; o >>= 1) {
        if (tid < o) red[tid] = fmaxf(red[tid], red[tid + o]);
        __syncthreads();
    }
    mx = red[0];
    for (int j = tid; j < NH; j += 256) {
        float e = expf(ts[j] - mx);
        g_e[b * NN + j] = e;
        g_e[b * NN + NH + j] = e;
    }
}

// ---------------------------------------------------------------------------
// Kernel 3: adj->uint8, per-row half-counts / e-denominators, final wA/wB.
// ---------------------------------------------------------------------------
__global__ __launch_bounds__(256) void k_aux(const int* __restrict__ adj) {
    int i = blockIdx.x;
    int tid = threadIdx.x;
    int lane = tid & 31, wid = tid >> 5;
    __shared__ float sc0[8], sc1[8];
    __shared__ float sdb[8][8];
    __shared__ float fc0s, fc1s;
    __shared__ float dtot[8];

    const int4* arow = (const int4*)(adj + (size_t)i * NN);
    uchar4* orow = (uchar4*)(g_adj8 + (size_t)i * NN);
    bool upper = (i >= NH);

    int c0 = 0, c1 = 0;
    float db[8] = {0.f, 0.f, 0.f, 0.f, 0.f, 0.f, 0.f, 0.f};

#pragma unroll
    for (int q = 0; q < 2; q++) {
        int idx4 = tid + q * 256;
        int4 v = arow[idx4];
        uchar4 m;
        m.x = v.x > 0; m.y = v.y > 0; m.z = v.z > 0; m.w = v.w > 0;
        orow[idx4] = m;
        int cnt = m.x + m.y + m.z + m.w;
        int j0 = idx4 * 4;
        if (j0 < NH) c0 += cnt; else c1 += cnt;
        if (upper) {
#pragma unroll
            for (int b = 0; b < 8; b++) {
                float4 ev = *(const float4*)(g_e + b * NN + j0);
                db[b] += (m.x ? ev.x : 0.f) + (m.y ? ev.y : 0.f)
                       + (m.z ? ev.z : 0.f) + (m.w ? ev.w : 0.f);
            }
        }
    }
#pragma unroll
    for (int o = 16; o > 0; o >>= 1) {
        c0 += __shfl_down_sync(0xffffffffu, c0, o);
        c1 += __shfl_down_sync(0xffffffffu, c1, o);
    }
    if (upper) {
#pragma unroll
        for (int b = 0; b < 8; b++)
#pragma unroll
            for (int o = 16; o > 0; o >>= 1)
                db[b] += __shfl_down_sync(0xffffffffu, db[b], o);
    }
    if (lane == 0) {
        sc0[wid] = (float)c0; sc1[wid] = (float)c1;
        if (upper) {
#pragma unroll
            for (int b = 0; b < 8; b++) sdb[wid][b] = db[b];
        }
    }
    __syncthreads();
    if (tid == 0) {
        float t0 = 0.f, t1 = 0.f;
#pragma unroll
        for (int w = 0; w < 8; w++) { t0 += sc0[w]; t1 += sc1[w]; }
        fc0s = t0; fc1s = t1;
    }
    if (upper && tid < 8) {
        float t = 0.f;
#pragma unroll
        for (int w = 0; w < 8; w++) t += sdb[w][tid];
        dtot[tid] = t;
    }
    __syncthreads();
    if (tid < 8) {
        int b = tid;
        float wA, wB;
        if (!upper) {
            float u0 = g_s1[b * NN + 2 * i] + g_s2[b * NN + 2 * i];
            float u1 = g_s1[b * NN + 2 * i + 1] + g_s2[b * NN + 2 * i + 1];
            u0 = u0 > 0.f ? u0 : 0.2f * u0;
            u1 = u1 > 0.f ? u1 : 0.2f * u1;
            float mv = fmaxf(u0, u1);
            float e0 = expf(u0 - mv);
            float e1 = expf(u1 - mv);
            float Z = fc0s * e0 + fc1s * e1;
            wA = e0 / Z;
            wB = e1 / Z;
        } else {
            float inv = 1.f / dtot[b];
            wA = inv;
            wB = inv;
        }
        g_w[0][b][i] = wA;
        g_w[1][b][i] = wB;
    }
}

// ---------------------------------------------------------------------------
// Kernel 3.5: g_Hv[1] = bf16(e*H). 8 floats per thread (2 float4, same row j).
// ---------------------------------------------------------------------------
__global__ __launch_bounds__(256) void k_conv() {
    int idx = blockIdx.x * 256 + threadIdx.x;
    int base = idx * 8;                      // 8 floats, within one row j
    float4 h0 = *(const float4*)&g_H[base];
    float4 h1 = *(const float4*)&g_H[base + 4];
    float e = g_e[base >> 6];                // (b*NN + j)
    uint4 o;
    o.x = pack2bf(h0.x * e, h0.y * e);
    o.y = pack2bf(h0.z * e, h0.w * e);
    o.z = pack2bf(h1.x * e, h1.y * e);
    o.w = pack2bf(h1.z * e, h1.w * e);
    *(uint4*)&g_Hv[1][base] = o;
}

// ---------------------------------------------------------------------------
// Kernel 4: tensor-core fused attention GEMM, double-buffered smem.
// out[b,i,:] = tanh( wA*Sum_{j<1024} adj*Bv + wB*Sum_{j>=1024} adj*Bv + bias ) + H
// Block: 128 rows x 64 cols, 8 warps (4m x 2n), warp 32x32, K-tile 64.
// One __syncthreads per K-tile; store of tile k+1 overlaps MMA of tile k.
// ---------------------------------------------------------------------------
__device__ __forceinline__ unsigned exp2b(unsigned v) {
    return (v & 1u) * 0x3F80u | ((v >> 8) & 1u) * 0x3F800000u;
}

__device__ __forceinline__ void st_expand(uint4 v, __nv_bfloat16* dst) {
    uint4 d0 = make_uint4(exp2b(v.x & 0xFFFFu), exp2b(v.x >> 16),
                          exp2b(v.y & 0xFFFFu), exp2b(v.y >> 16));
    uint4 d1 = make_uint4(exp2b(v.z & 0xFFFFu), exp2b(v.z >> 16),
                          exp2b(v.w & 0xFFFFu), exp2b(v.w >> 16));
    ((uint4*)dst)[0] = d0;
    ((uint4*)dst)[1] = d1;
}

#define LDSM4(R, ADDR)                                                         \
    asm volatile("ldmatrix.sync.aligned.m8n8.x4.shared.b16 {%0,%1,%2,%3}, [%4];" \
                 : "=r"(R[0]), "=r"(R[1]), "=r"(R[2]), "=r"(R[3]) : "r"(ADDR))

#define LDSM4T(R, ADDR)                                                        \
    asm volatile("ldmatrix.sync.aligned.m8n8.x4.trans.shared.b16 {%0,%1,%2,%3}, [%4];" \
                 : "=r"(R[0]), "=r"(R[1]), "=r"(R[2]), "=r"(R[3]) : "r"(ADDR))

#define MMA16816(C, AR, B0, B1)                                                \
    asm volatile(                                                              \
        "mma.sync.aligned.m16n8k16.row.col.f32.bf16.bf16.f32 "                 \
        "{%0,%1,%2,%3}, {%4,%5,%6,%7}, {%8,%9}, {%0,%1,%2,%3};"                \
        : "+f"(C[0]), "+f"(C[1]), "+f"(C[2]), "+f"(C[3])                       \
        : "r"(AR[0]), "r"(AR[1]), "r"(AR[2]), "r"(AR[3]), "r"(B0), "r"(B1))

#define TILE_BODY(ACC)                                                         \
    {                                                                          \
        unsigned aSel = (kt & 1) ? A_BUF_BYTES : 0;                            \
        unsigned bSel = (kt & 1) ? B_BUF_BYTES : 0;                            \
        /* prefetch tile kt+1 from global */                                   \
        if (kt + 1 < 32) {                                                     \
            const unsigned char* ap = aGbase + (kt + 1) * 64;                  \
            pa0 = *(const uint4*)ap;                                           \
            pa1 = *(const uint4*)(ap + 16);                                    \
            const uint4* bp = (const uint4*)(HvB + ((kt + 1) * 64 + br) * DD); \
            pb0 = bp[bi1];                                                     \
            pb1 = bp[bi2];                                                     \
        }                                                                      \
        /* MMAs on buffer (kt&1) */                                            \
        _Pragma("unroll")                                                      \
        for (int k16 = 0; k16 < 4; k16++) {                                    \
            unsigned a0[4], a1[4], f0[4], f1[4];                               \
            LDSM4(a0, aA0 + aSel + k16 * 32);                                  \
            LDSM4(a1, aA1 + aSel + k16 * 32);                                  \
            LDSM4T(f0, aB0 + bSel + k16 * 16 * BSTR * 2);                      \
            LDSM4T(f1, aB1 + bSel + k16 * 16 * BSTR * 2);                      \
            MMA16816(ACC[0][0], a0, f0[0], f0[1]);                             \
            MMA16816(ACC[0][1], a0, f0[2], f0[3]);                             \
            MMA16816(ACC[0][2], a0, f1[0], f1[1]);                             \
            MMA16816(ACC[0][3], a0, f1[2], f1[3]);                             \
            MMA16816(ACC[1][0], a1, f0[0], f0[1]);                             \
            MMA16816(ACC[1][1], a1, f0[2], f0[3]);                             \
            MMA16816(ACC[1][2], a1, f1[0], f1[1]);                             \
            MMA16816(ACC[1][3], a1, f1[2], f1[3]);                             \
        }                                                                      \
        /* store tile kt+1 into the other buffer */                            \
        if (kt + 1 < 32) {                                                     \
            __nv_bfloat16* Ad = (__nv_bfloat16*)(dsm + (aSel ^ A_BUF_BYTES));  \
            __nv_bfloat16* Bd = (__nv_bfloat16*)(dsm + B_BASE_OFF + (bSel ^ B_BUF_BYTES)); \
            st_expand(pa0, &Ad[arA]);                                          \
            st_expand(pa1, &Ad[arA + 16]);                                     \
            *(uint4*)&Bd[brB] = pb0;                                           \
            *(uint4*)&Bd[brB + 32] = pb1;                                      \
        }                                                                      \
        __syncthreads();                                                       \
    }

__global__ __launch_bounds__(256) void k_main(const float* __restrict__ bias,
                                              float* __restrict__ out) {
    extern __shared__ __align__(16) char dsm[];
    __shared__ float wAs[128], wBs[128];

    int tid = threadIdx.x;
    int lane = tid & 31, warp = tid >> 5;
    int wm = warp & 3, wn = warp >> 2;
    int b = blockIdx.y;
    int i0 = blockIdx.x * 128;
    bool upper = (i0 >= NH);

    if (tid < 128) {
        wAs[tid] = g_w[0][b][i0 + tid];
        wBs[tid] = g_w[1][b][i0 + tid];
    }

    const __nv_bfloat16* HvB = g_Hv[upper ? 1 : 0] + (size_t)b * NN * DD;

    // A staging: 128 rows x 64 bytes; thread -> (row, 32-byte half)
    int ar = tid >> 1;
    int ak = (tid & 1) * 32;
    int arA = ar * ASTR + ak;
    const unsigned char* aGbase = g_adj8 + (size_t)(i0 + ar) * NN + ak;

    // B staging: 64 rows x 128 bytes; thread -> (row, two uint4 slots)
    int br = tid >> 2;
    int bi1 = tid & 3, bi2 = bi1 + 4;
    int brB = br * BSTR + bi1 * 8;

    unsigned asb = (unsigned)__cvta_generic_to_shared(dsm);
    unsigned bsb = asb + B_BASE_OFF;
    unsigned aA0 = asb + (unsigned)(((wm * 32 + (lane & 15)) * ASTR + (lane >> 4) * 8) * 2);
    unsigned aA1 = aA0 + 16 * ASTR * 2;
    unsigned aB0 = bsb + (unsigned)(((lane & 15) * BSTR + wn * 32 + (lane >> 4) * 8) * 2);
    unsigned aB1 = aB0 + 32;

    // preload tile 0 and stage into buffer 0
    uint4 pa0 = *(const uint4*)aGbase;
    uint4 pa1 = *(const uint4*)(aGbase + 16);
    const uint4* bp0 = (const uint4*)(HvB + br * DD);
    uint4 pb0 = bp0[bi1], pb1 = bp0[bi2];
    {
        __nv_bfloat16* Ad = (__nv_bfloat16*)dsm;
        __nv_bfloat16* Bd = (__nv_bfloat16*)(dsm + B_BASE_OFF);
        st_expand(pa0, &Ad[arA]);
        st_expand(pa1, &Ad[arA + 16]);
        *(uint4*)&Bd[brB] = pb0;
        *(uint4*)&Bd[brB + 32] = pb1;
    }
    __syncthreads();

    float accLo[2][4][4] = {};
    float accHi[2][4][4] = {};

    for (int kt = 0; kt < 16; kt++) TILE_BODY(accLo);
    for (int kt = 16; kt < 32; kt++) TILE_BODY(accHi);

    // epilogue: out = tanh(wA*accLo + wB*accHi + bias) + H
    int gID = lane >> 2, tig = lane & 3;
#pragma unroll
    for (int mt = 0; mt < 2; mt++) {
#pragma unroll
        for (int nt = 0; nt < 4; nt++) {
            int c = wn * 32 + nt * 8 + tig * 2;
            float bx = bias[c], by = bias[c + 1];
#pragma unroll
            for (int hseg = 0; hseg < 2; hseg++) {
                int r = wm * 32 + mt * 16 + gID + hseg * 8;
                float wa = wAs[r], wb = wBs[r];
                int ci = hseg * 2;
                float vx = wa * accLo[mt][nt][ci]     + wb * accHi[mt][nt][ci]     + bx;
                float vy = wa * accLo[mt][nt][ci + 1] + wb * accHi[mt][nt][ci + 1] + by;
                size_t o = ((size_t)b * NN + i0 + r) * DD + c;
                float2 h2 = *(const float2*)&g_H[o];
                float2 ov;
                ov.x = tanhf(vx) + h2.x;
                ov.y = tanhf(vy) + h2.y;
                *(float2*)&out[o] = ov;
            }
        }
    }
}

// ---------------------------------------------------------------------------
extern "C" void kernel_launch(void* const* d_in, const int* in_sizes, int n_in,
                              void* d_out, int out_size) {
    const float* x    = nullptr;
    const int*   adj  = nullptr;
    const float* Wm   = nullptr;
    const float* av   = nullptr;
    const float* bias = nullptr;
    for (int i = 0; i < n_in; i++) {
        switch (in_sizes[i]) {
            case BB * NN * CC: x    = (const float*)d_in[i]; break;
            case NN * NN:      adj  = (const int*)d_in[i];   break;
            case CC * DD:      Wm   = (const float*)d_in[i]; break;
            case 2 * DD:       av   = (const float*)d_in[i]; break;
            case DD:           bias = (const float*)d_in[i]; break;
            default: break;
        }
    }
    if (!x || !adj || !Wm || !av || !bias) return;
    float* out = (float*)d_out;

    cudaFuncSetAttribute(k_main, cudaFuncAttributeMaxDynamicSharedMemorySize,
                         DSMEM_BYTES);

    k_hidden<<<BB * NN / 64, 256>>>(x, Wm, av);
    k_prep<<<BB, 256>>>();
    k_aux<<<NN, 256>>>(adj);
    k_conv<<<(BB * NN * DD) / 2048, 256>>>();
    k_main<<<dim3(NN / 128, BB), 256, DSMEM_BYTES>>>(bias, out);
}